// round 16
// baseline (speedup 1.0000x reference)
#include <cuda_runtime.h>
#include <math.h>

#define BB 32
#define H0 256
#define W0 512
#define NT 128            // 4 warps per block
#define FULLMASK 0xffffffffu

// fused warp layout, per side: L0 2304, L1 576, L2 160, L3 96 = 3136
#define L1_BASE 2304
#define L2_BASE 2880
#define L3_BASE 3040
#define SIDE_WARPS 3136
#define TOTAL_WARPS (SIDE_WARPS * 2)
#define NFUSED (TOTAL_WARPS / 4)    // 1568 fused blocks; all level/side boundaries block-aligned

// pyramid stage block counts (128 threads x 8 elems = 1024 elems/block)
#define PYR1B 6144    // 2*96*128*256 / 1024
#define PYR2B 1536
#define PYR3B 384
#define PYRTOT (PYR1B + PYR2B + PYR3B)   // 8064
#define GRID (PYRTOT + NFUSED)           // 9632

// ---------------- scratch ----------------
__device__ float g_lp1[BB*3*128*256];
__device__ float g_rp1[BB*3*128*256];
__device__ float g_lp2[BB*3*64*128];
__device__ float g_rp2[BB*3*64*128];
__device__ float g_lp3[BB*3*32*64];
__device__ float g_rp3[BB*3*32*64];

// per level i, 8 slots: 0 dssim_l, 1 dssim_r, 2 l1_l, 3 l1_r, 4 lr_l, 5 lr_r, 6 ds_l, 7 ds_r
__device__ double g_acc[32];
__device__ int g_done = 0;
__device__ unsigned int g_cnt[3];

// ---------------- reduction helper (stride-2 slots) ----------------
template<int NV>
__device__ __forceinline__ void block_accumulate2(float (&v)[NV], double* accs) {
    #pragma unroll
    for (int k = 0; k < NV; k++)
        #pragma unroll
        for (int o = 16; o > 0; o >>= 1)
            v[k] += __shfl_down_sync(FULLMASK, v[k], o);
    __shared__ float sh[NV][4];
    int lane = threadIdx.x & 31, w = threadIdx.x >> 5;
    if (lane == 0) {
        #pragma unroll
        for (int k = 0; k < NV; k++) sh[k][w] = v[k];
    }
    __syncthreads();
    if (threadIdx.x == 0) {
        #pragma unroll
        for (int k = 0; k < NV; k++) {
            float s = sh[k][0] + sh[k][1] + sh[k][2] + sh[k][3];
            atomicAdd(accs + 2 * k, (double)s);
        }
    }
}

// ---------------- bilinear align-corners resize element ----------------
__device__ __forceinline__ void resize_elem(const float* __restrict__ src, float* __restrict__ dst,
                                            int idx, int h, int w, int nh, int nw) {
    int x  = idx % nw;
    int t  = idx / nw;
    int y  = t % nh;
    int bc = t / nh;
    float fy = (float)y * (float)(h - 1) / (float)(nh - 1);
    float fx = (float)x * (float)(w - 1) / (float)(nw - 1);
    int y0 = (int)floorf(fy); int y1 = min(y0 + 1, h - 1);
    int x0 = (int)floorf(fx); int x1 = min(x0 + 1, w - 1);
    float wy = fy - (float)y0, wx = fx - (float)x0;
    const float* s = src + (size_t)bc * h * w;
    float top = s[(size_t)y0 * w + x0] * (1.f - wx) + s[(size_t)y0 * w + x1] * wx;
    float bot = s[(size_t)y1 * w + x0] * (1.f - wx) + s[(size_t)y1 * w + x1] * wx;
    dst[idx] = top * (1.f - wy) + bot * wy;
}

// ---------------- everything in one launch ----------------
struct LevelArgs {
    const float* lp[4];
    const float* rp[4];
    const float* disp[4];
};

struct Row {
    float d;
    float o0, o1, wf;
    float a[3];
    float e0[3], e1[3];
};

__global__ __launch_bounds__(NT) void mono_kernel(LevelArgs args,
                                                  const float* __restrict__ left,
                                                  const float* __restrict__ right,
                                                  float* __restrict__ out) {
    const int BC = BB * 3;
    int bid = blockIdx.x;
    int tid = threadIdx.x;

    // ================= pyramid stages =================
    if (bid < PYRTOT) {
        if (bid < PYR1B) {
            if (bid == 0 && tid < 32) g_acc[tid] = 0.0;
            int total = BC * 128 * 256;
            #pragma unroll
            for (int e = 0; e < 8; e++) {
                int gid = bid * 1024 + e * 128 + tid;
                if (gid < total) resize_elem(left,  g_lp1, gid,         256, 512, 128, 256);
                else             resize_elem(right, g_rp1, gid - total, 256, 512, 128, 256);
            }
            __threadfence();
            __syncthreads();
            if (tid == 0) atomicAdd(&g_cnt[0], 1u);
        } else if (bid < PYR1B + PYR2B) {
            if (tid == 0)
                while (atomicAdd(&g_cnt[0], 0u) < PYR1B) __nanosleep(60);
            __syncthreads();
            int total = BC * 64 * 128;
            #pragma unroll
            for (int e = 0; e < 8; e++) {
                int gid = (bid - PYR1B) * 1024 + e * 128 + tid;
                if (gid < total) resize_elem(g_lp1, g_lp2, gid,         128, 256, 64, 128);
                else             resize_elem(g_rp1, g_rp2, gid - total, 128, 256, 64, 128);
            }
            __threadfence();
            __syncthreads();
            if (tid == 0) atomicAdd(&g_cnt[1], 1u);
        } else {
            if (tid == 0)
                while (atomicAdd(&g_cnt[1], 0u) < PYR2B) __nanosleep(60);
            __syncthreads();
            int total = BC * 32 * 64;
            #pragma unroll
            for (int e = 0; e < 8; e++) {
                int gid = (bid - PYR1B - PYR2B) * 1024 + e * 128 + tid;
                if (gid < total) resize_elem(g_lp2, g_lp3, gid,         64, 128, 32, 64);
                else             resize_elem(g_rp2, g_rp3, gid - total, 64, 128, 32, 64);
            }
            __threadfence();
            __syncthreads();
            if (tid == 0) atomicAdd(&g_cnt[2], 1u);
        }
        return;
    }

    // ================= fused loss =================
    int lane = tid & 31;
    int g = (bid - PYRTOT) * (NT / 32) + (tid >> 5);
    int side = (g >= SIDE_WARPS) ? 1 : 0;
    g -= side * SIDE_WARPS;

    int lvl, base, wpi, nx, W, H, CH;
    if (g < L1_BASE)      { lvl = 0; base = 0;       wpi = 72; nx = 18; W = 512; H = 256; CH = 64; }
    else if (g < L2_BASE) { lvl = 1; base = L1_BASE; wpi = 18; nx = 9;  W = 256; H = 128; CH = 64; }
    else if (g < L3_BASE) { lvl = 2; base = L2_BASE; wpi = 5;  nx = 5;  W = 128; H = 64;  CH = 64; }
    else                  { lvl = 3; base = L3_BASE; wpi = 3;  nx = 3;  W = 64;  H = 32;  CH = 32; }

    // levels 1-3 depend on pyramid completion (lvl is block-uniform)
    if (lvl != 0) {
        if (tid == 0)
            while (atomicAdd(&g_cnt[2], 0u) < PYR3B) __nanosleep(60);
        __syncthreads();
    }

    int r   = g - base;
    int b   = r / wpi;
    int rr  = r - b * wpi;
    int xsl = rr % nx;
    int ych = rr / nx;
    int y0  = ych * CH;
    int x   = xsl * 30 + lane - 1;

    int plane = H * W;
    const float* Ximg = side ? args.rp[lvl] : args.lp[lvl];
    const float* Gimg = side ? args.lp[lvl] : args.rp[lvl];
    const float* dbase = args.disp[lvl] + (size_t)b * 2 * plane;
    const float* dmy  = dbase + (side ? plane : 0);
    const float* doth = dbase + (side ? 0 : plane);
    float sgn = side ? (float)(W - 1) : -(float)(W - 1);

    bool inx = (x >= 0) & (x < W);
    bool lane_emit = (lane >= 1) & (lane <= 30) & (x < W);
    bool dss_x = lane_emit & (x >= 1) & (x <= W - 2);

    int ys = max(y0 - 2, 0);
    int ye = min(y0 + CH, H - 1);

    const float* Xb[3];
    const float* Gb[3];
    #pragma unroll
    for (int c = 0; c < 3; c++) {
        Xb[c] = Ximg + ((size_t)b * 3 + c) * plane;
        Gb[c] = Gimg + ((size_t)b * 3 + c) * plane;
    }

    auto issue = [&](int y, float d) -> Row {
        Row rv;
        rv.d = d;
        float xwf = (float)x + d * sgn;
        float fw = floorf(xwf); int x0i = (int)fw; float wf = xwf - fw;
        bool v0 = (x0i >= 0) & (x0i < W);
        bool v1 = (x0i >= -1) & (x0i < W - 1);
        rv.wf = wf;
        int off = y * W;
        rv.o0 = v0 ? __ldg(doth + off + x0i) : 0.f;
        rv.o1 = v1 ? __ldg(doth + off + x0i + 1) : 0.f;
        #pragma unroll
        for (int c = 0; c < 3; c++) {
            rv.a[c]  = inx ? __ldg(Xb[c] + off + x) : 0.f;
            rv.e0[c] = v0 ? __ldg(Gb[c] + off + x0i) : 0.f;
            rv.e1[c] = v1 ? __ldg(Gb[c] + off + x0i + 1) : 0.f;
        }
        return rv;
    };

    float s2[3][5], s1[3][5];
    #pragma unroll
    for (int c = 0; c < 3; c++)
        #pragma unroll
        for (int k = 0; k < 5; k++) { s2[c][k] = 0.f; s1[c][k] = 0.f; }
    float pX[3] = {0.f, 0.f, 0.f};
    float pd = 0.f;

    float v[4] = {0.f, 0.f, 0.f, 0.f};   // dssim, l1, lr, ds
    const float inv9 = 1.f / 9.f;
    const float C1v = 1e-4f, C2v = 9e-4f, third = 1.f / 3.f;

    auto process = [&](int y, const Row& cur) {
        float d = cur.d;
        float w1 = cur.wf, w0 = 1.f - cur.wf;
        float oth = cur.o0 * w0 + cur.o1 * w1;
        float nd = __shfl_down_sync(FULLMASK, d, 1);

        float Xv[3], Ev[3], nXv[3], hs[3][5];
        #pragma unroll
        for (int c = 0; c < 3; c++) {
            float a = cur.a[c];
            float e = cur.e0[c] * w0 + cur.e1[c] * w1;
            Xv[c] = a; Ev[c] = e;
            float am = __shfl_up_sync(FULLMASK, a, 1);
            float ap = __shfl_down_sync(FULLMASK, a, 1);
            float em = __shfl_up_sync(FULLMASK, e, 1);
            float ep = __shfl_down_sync(FULLMASK, e, 1);
            nXv[c] = ap;
            hs[c][0] = (am + a) + ap;
            hs[c][1] = (em + e) + ep;
            hs[c][2] = (am * am + a * a) + ap * ap;
            hs[c][3] = (em * em + e * e) + ep * ep;
            hs[c][4] = (am * em + a * e) + ap * ep;
        }

        bool own  = (y >= y0) & (y < y0 + CH);
        bool ownp = (y - 1 >= y0) & (y - 1 < y0 + CH);

        if (lane_emit) {
            if (own) {
                v[1] += fabsf(Xv[0] - Ev[0]) + fabsf(Xv[1] - Ev[1]) + fabsf(Xv[2] - Ev[2]);
                v[2] += fabsf(d - oth);
                if (x < W - 1) {
                    float gx = fabsf(Xv[0]-nXv[0]) + fabsf(Xv[1]-nXv[1]) + fabsf(Xv[2]-nXv[2]);
                    v[3] += fabsf((d - nd) * __expf(-gx * third));
                }
            }
            if (ownp) {
                float gy = fabsf(pX[0]-Xv[0]) + fabsf(pX[1]-Xv[1]) + fabsf(pX[2]-Xv[2]);
                v[3] += fabsf((pd - d) * __expf(-gy * third));
            }
            if (ownp & (y - 1 >= 1) & (y - 1 <= H - 2) & dss_x) {
                #pragma unroll
                for (int c = 0; c < 3; c++) {
                    float Sa  = s2[c][0] + hs[c][0];
                    float Se  = s2[c][1] + hs[c][1];
                    float Saa = s2[c][2] + hs[c][2];
                    float See = s2[c][3] + hs[c][3];
                    float Sae = s2[c][4] + hs[c][4];
                    float mux = Sa * inv9, muy = Se * inv9;
                    float sigx = Saa * inv9 - mux * mux;
                    float sigy = See * inv9 - muy * muy;
                    float cov  = Sae * inv9 - mux * muy;
                    float ssim = __fdividef((2.f*mux*muy + C1v) * (2.f*cov + C2v),
                                            (mux*mux + muy*muy + C1v) * (sigx + sigy + C2v));
                    v[0] += __saturatef((1.f - ssim) * 0.5f);
                }
            }
        }

        #pragma unroll
        for (int c = 0; c < 3; c++)
            #pragma unroll
            for (int k = 0; k < 5; k++) {
                float t = hs[c][k];
                s2[c][k] = s1[c][k] + t;
                s1[c][k] = t;
            }
        pX[0] = Xv[0]; pX[1] = Xv[1]; pX[2] = Xv[2];
        pd = d;
    };

    // ---- pipeline prologue ----
    float dB = (ys + 1 <= ye) ? (inx ? __ldg(dmy + (ys + 1) * W + x) : 0.f) : 0.f;
    Row cur = issue(ys, inx ? __ldg(dmy + ys * W + x) : 0.f);
    Row nxt;

    for (int y = ys; y <= ye; y++) {
        float dC = (y + 2 <= ye) ? (inx ? __ldg(dmy + (y + 2) * W + x) : 0.f) : 0.f;
        if (y + 1 <= ye) nxt = issue(y + 1, dB);

        process(y, cur);

        cur = nxt;
        dB = dC;
    }

    block_accumulate2<4>(v, g_acc + lvl * 8 + side);

    // ---- last fused block: final combine + counter reset for next replay ----
    if (tid == 0) {
        __threadfence();
        int t = atomicAdd(&g_done, 1);
        if (t == NFUSED - 1) {
            g_done = 0;
            g_cnt[0] = 0; g_cnt[1] = 0; g_cnt[2] = 0;
            __threadfence();
            double AP = 0.0, LR = 0.0, DS = 0.0;
            for (int i = 0; i < 4; i++) {
                int Hi = H0 >> i, Wi = W0 >> i;
                double Nd = (double)BB * 3.0 * (Hi - 2) * (Wi - 2);
                double Nl = (double)BB * 3.0 * Hi * Wi;
                double Np = (double)BB * Hi * Wi;
                const double* a = g_acc + i * 8;
                AP += 0.85 * (a[0] + a[1]) / Nd + 0.15 * (a[2] + a[3]) / Nl;
                LR += (a[4] + a[5]) / Np;
                DS += (a[6] + a[7]) / Np / (double)(1 << i);
            }
            AP *= 0.85;
            DS *= 0.1;
            double total = AP + LR + DS;
            out[0] = (float)total;
            out[1] = (float)AP;
            out[2] = (float)LR;
            out[3] = (float)DS;
        }
    }
}

// ---------------- host launcher ----------------
extern "C" void kernel_launch(void* const* d_in, const int* in_sizes, int n_in,
                              void* d_out, int out_size) {
    const float* disp0 = (const float*)d_in[0];
    const float* disp1 = (const float*)d_in[1];
    const float* disp2 = (const float*)d_in[2];
    const float* disp3 = (const float*)d_in[3];
    const float* left  = (const float*)d_in[4];
    const float* right = (const float*)d_in[5];
    float* out = (float*)d_out;

    static bool init = false;
    static float *lp1, *rp1, *lp2, *rp2, *lp3, *rp3;
    if (!init) {
        cudaGetSymbolAddress((void**)&lp1, g_lp1);
        cudaGetSymbolAddress((void**)&rp1, g_rp1);
        cudaGetSymbolAddress((void**)&lp2, g_lp2);
        cudaGetSymbolAddress((void**)&rp2, g_rp2);
        cudaGetSymbolAddress((void**)&lp3, g_lp3);
        cudaGetSymbolAddress((void**)&rp3, g_rp3);
        init = true;
    }

    LevelArgs args;
    args.lp[0] = left;  args.lp[1] = lp1; args.lp[2] = lp2; args.lp[3] = lp3;
    args.rp[0] = right; args.rp[1] = rp1; args.rp[2] = rp2; args.rp[3] = rp3;
    args.disp[0] = disp0; args.disp[1] = disp1; args.disp[2] = disp2; args.disp[3] = disp3;

    mono_kernel<<<GRID, NT>>>(args, left, right, out);
}

// round 17
// speedup vs baseline: 1.2348x; 1.2348x over previous
#include <cuda_runtime.h>
#include <math.h>

#define BB 32
#define H0 256
#define W0 512
#define NT 128            // 4 warps per block
#define FULLMASK 0xffffffffu

#define SIDE_WARPS 3136
// mode 0 (L0): per-side 2304 warps -> 4608 warps -> 1152 blocks
// mode 1 (L1-3): per-side 832 warps (L1 576, L2 160, L3 96) -> 1664 warps -> 416 blocks
#define L0_BLOCKS 1152
#define L123_BLOCKS 416

// ---------------- scratch ----------------
__device__ float g_lp1[BB*3*128*256];
__device__ float g_rp1[BB*3*128*256];
__device__ float g_lp2[BB*3*64*128];
__device__ float g_rp2[BB*3*64*128];
__device__ float g_lp3[BB*3*32*64];
__device__ float g_rp3[BB*3*32*64];

// per level i, 8 slots: 0 dssim_l, 1 dssim_r, 2 l1_l, 3 l1_r, 4 lr_l, 5 lr_r, 6 ds_l, 7 ds_r
__device__ double g_acc[32];   // static-zero at load; reset by tail block each run
__device__ int g_done = 0;

// ---------------- reduction helper (stride-2 slots) ----------------
template<int NV>
__device__ __forceinline__ void block_accumulate2(float (&v)[NV], double* accs) {
    #pragma unroll
    for (int k = 0; k < NV; k++)
        #pragma unroll
        for (int o = 16; o > 0; o >>= 1)
            v[k] += __shfl_down_sync(FULLMASK, v[k], o);
    __shared__ float sh[NV][4];
    int lane = threadIdx.x & 31, w = threadIdx.x >> 5;
    if (lane == 0) {
        #pragma unroll
        for (int k = 0; k < NV; k++) sh[k][w] = v[k];
    }
    __syncthreads();
    if (threadIdx.x == 0) {
        #pragma unroll
        for (int k = 0; k < NV; k++) {
            float s = sh[k][0] + sh[k][1] + sh[k][2] + sh[k][3];
            atomicAdd(accs + 2 * k, (double)s);
        }
    }
}

// ---------------- paired bilinear align-corners resize ----------------
__global__ void resize2_kernel(const float* __restrict__ srcA, float* __restrict__ dstA,
                               const float* __restrict__ srcB, float* __restrict__ dstB,
                               int BC, int h, int w, int nh, int nw) {
    int idx = blockIdx.x * blockDim.x + threadIdx.x;
    int total = BC * nh * nw;
    int which = 0;
    if (idx >= total) { idx -= total; which = 1; if (idx >= total) return; }
    const float* src = which ? srcB : srcA;
    float* dst = which ? dstB : dstA;
    int x  = idx % nw;
    int t  = idx / nw;
    int y  = t % nh;
    int bc = t / nh;
    float fy = (float)y * (float)(h - 1) / (float)(nh - 1);
    float fx = (float)x * (float)(w - 1) / (float)(nw - 1);
    int y0 = (int)floorf(fy); int y1 = min(y0 + 1, h - 1);
    int x0 = (int)floorf(fx); int x1 = min(x0 + 1, w - 1);
    float wy = fy - (float)y0, wx = fx - (float)x0;
    const float* s = src + (size_t)bc * h * w;
    float top = s[(size_t)y0 * w + x0] * (1.f - wx) + s[(size_t)y0 * w + x1] * wx;
    float bot = s[(size_t)y1 * w + x0] * (1.f - wx) + s[(size_t)y1 * w + x1] * wx;
    dst[idx] = top * (1.f - wy) + bot * wy;
}

// ---------------- fused loss: side-split + 2-stage pipeline (R10 body) ------
struct LevelArgs {
    const float* lp[4];
    const float* rp[4];
    const float* disp[4];
};

struct Row {
    float d;
    float o0, o1, wf;
    float a[3];
    float e0[3], e1[3];
};

__global__ __launch_bounds__(NT) void fused_kernel(LevelArgs args, int mode, float* __restrict__ out) {
    int tid = threadIdx.x;
    int lane = tid & 31;
    int gg = blockIdx.x * (NT / 32) + (tid >> 5);

    int side, lvl, r, wpi, nx, W, H, CH;
    if (mode == 0) {
        side = (gg >= 2304) ? 1 : 0;
        r = gg - side * 2304;
        lvl = 0; wpi = 72; nx = 18; W = 512; H = 256; CH = 64;
    } else {
        side = (gg >= 832) ? 1 : 0;
        int gl = gg - side * 832;
        if (gl < 576)      { lvl = 1; r = gl;       wpi = 18; nx = 9; W = 256; H = 128; CH = 64; }
        else if (gl < 736) { lvl = 2; r = gl - 576; wpi = 5;  nx = 5; W = 128; H = 64;  CH = 64; }
        else               { lvl = 3; r = gl - 736; wpi = 3;  nx = 3; W = 64;  H = 32;  CH = 32; }
    }

    int b   = r / wpi;
    int rr  = r - b * wpi;
    int xsl = rr % nx;
    int ych = rr / nx;
    int y0  = ych * CH;
    int x   = xsl * 30 + lane - 1;

    int plane = H * W;
    const float* Ximg = side ? args.rp[lvl] : args.lp[lvl];
    const float* Gimg = side ? args.lp[lvl] : args.rp[lvl];
    const float* dbase = args.disp[lvl] + (size_t)b * 2 * plane;
    const float* dmy  = dbase + (side ? plane : 0);
    const float* doth = dbase + (side ? 0 : plane);
    float sgn = side ? (float)(W - 1) : -(float)(W - 1);

    bool inx = (x >= 0) & (x < W);
    bool lane_emit = (lane >= 1) & (lane <= 30) & (x < W);
    bool dss_x = lane_emit & (x >= 1) & (x <= W - 2);

    int ys = max(y0 - 2, 0);
    int ye = min(y0 + CH, H - 1);

    const float* Xb[3];
    const float* Gb[3];
    #pragma unroll
    for (int c = 0; c < 3; c++) {
        Xb[c] = Ximg + ((size_t)b * 3 + c) * plane;
        Gb[c] = Gimg + ((size_t)b * 3 + c) * plane;
    }

    auto issue = [&](int y, float d) -> Row {
        Row rv;
        rv.d = d;
        float xwf = (float)x + d * sgn;
        float fw = floorf(xwf); int x0i = (int)fw; float wf = xwf - fw;
        bool v0 = (x0i >= 0) & (x0i < W);
        bool v1 = (x0i >= -1) & (x0i < W - 1);
        rv.wf = wf;
        int off = y * W;
        rv.o0 = v0 ? __ldg(doth + off + x0i) : 0.f;
        rv.o1 = v1 ? __ldg(doth + off + x0i + 1) : 0.f;
        #pragma unroll
        for (int c = 0; c < 3; c++) {
            rv.a[c]  = inx ? __ldg(Xb[c] + off + x) : 0.f;
            rv.e0[c] = v0 ? __ldg(Gb[c] + off + x0i) : 0.f;
            rv.e1[c] = v1 ? __ldg(Gb[c] + off + x0i + 1) : 0.f;
        }
        return rv;
    };

    float s2[3][5], s1[3][5];
    #pragma unroll
    for (int c = 0; c < 3; c++)
        #pragma unroll
        for (int k = 0; k < 5; k++) { s2[c][k] = 0.f; s1[c][k] = 0.f; }
    float pX[3] = {0.f, 0.f, 0.f};
    float pd = 0.f;

    float v[4] = {0.f, 0.f, 0.f, 0.f};   // dssim, l1, lr, ds
    const float inv9 = 1.f / 9.f;
    const float C1v = 1e-4f, C2v = 9e-4f, third = 1.f / 3.f;

    auto process = [&](int y, const Row& cur) {
        float d = cur.d;
        float w1 = cur.wf, w0 = 1.f - cur.wf;
        float oth = cur.o0 * w0 + cur.o1 * w1;
        float nd = __shfl_down_sync(FULLMASK, d, 1);

        float Xv[3], Ev[3], nXv[3], hs[3][5];
        #pragma unroll
        for (int c = 0; c < 3; c++) {
            float a = cur.a[c];
            float e = cur.e0[c] * w0 + cur.e1[c] * w1;
            Xv[c] = a; Ev[c] = e;
            float am = __shfl_up_sync(FULLMASK, a, 1);
            float ap = __shfl_down_sync(FULLMASK, a, 1);
            float em = __shfl_up_sync(FULLMASK, e, 1);
            float ep = __shfl_down_sync(FULLMASK, e, 1);
            nXv[c] = ap;
            hs[c][0] = (am + a) + ap;
            hs[c][1] = (em + e) + ep;
            hs[c][2] = (am * am + a * a) + ap * ap;
            hs[c][3] = (em * em + e * e) + ep * ep;
            hs[c][4] = (am * em + a * e) + ap * ep;
        }

        bool own  = (y >= y0) & (y < y0 + CH);
        bool ownp = (y - 1 >= y0) & (y - 1 < y0 + CH);

        if (lane_emit) {
            if (own) {
                v[1] += fabsf(Xv[0] - Ev[0]) + fabsf(Xv[1] - Ev[1]) + fabsf(Xv[2] - Ev[2]);
                v[2] += fabsf(d - oth);
                if (x < W - 1) {
                    float gx = fabsf(Xv[0]-nXv[0]) + fabsf(Xv[1]-nXv[1]) + fabsf(Xv[2]-nXv[2]);
                    v[3] += fabsf((d - nd) * __expf(-gx * third));
                }
            }
            if (ownp) {
                float gy = fabsf(pX[0]-Xv[0]) + fabsf(pX[1]-Xv[1]) + fabsf(pX[2]-Xv[2]);
                v[3] += fabsf((pd - d) * __expf(-gy * third));
            }
            if (ownp & (y - 1 >= 1) & (y - 1 <= H - 2) & dss_x) {
                #pragma unroll
                for (int c = 0; c < 3; c++) {
                    float Sa  = s2[c][0] + hs[c][0];
                    float Se  = s2[c][1] + hs[c][1];
                    float Saa = s2[c][2] + hs[c][2];
                    float See = s2[c][3] + hs[c][3];
                    float Sae = s2[c][4] + hs[c][4];
                    float mux = Sa * inv9, muy = Se * inv9;
                    float sigx = Saa * inv9 - mux * mux;
                    float sigy = See * inv9 - muy * muy;
                    float cov  = Sae * inv9 - mux * muy;
                    float ssim = __fdividef((2.f*mux*muy + C1v) * (2.f*cov + C2v),
                                            (mux*mux + muy*muy + C1v) * (sigx + sigy + C2v));
                    v[0] += __saturatef((1.f - ssim) * 0.5f);
                }
            }
        }

        #pragma unroll
        for (int c = 0; c < 3; c++)
            #pragma unroll
            for (int k = 0; k < 5; k++) {
                float t = hs[c][k];
                s2[c][k] = s1[c][k] + t;
                s1[c][k] = t;
            }
        pX[0] = Xv[0]; pX[1] = Xv[1]; pX[2] = Xv[2];
        pd = d;
    };

    // ---- pipeline prologue ----
    float dB = (ys + 1 <= ye) ? (inx ? __ldg(dmy + (ys + 1) * W + x) : 0.f) : 0.f;
    Row cur = issue(ys, inx ? __ldg(dmy + ys * W + x) : 0.f);
    Row nxt;

    for (int y = ys; y <= ye; y++) {
        float dC = (y + 2 <= ye) ? (inx ? __ldg(dmy + (y + 2) * W + x) : 0.f) : 0.f;
        if (y + 1 <= ye) nxt = issue(y + 1, dB);

        process(y, cur);

        cur = nxt;
        dB = dC;
    }

    block_accumulate2<4>(v, g_acc + lvl * 8 + side);

    // ---- tail block of mode-1 kernel: final combine + self-clean ----
    if (mode == 1 && tid == 0) {
        __threadfence();
        int t = atomicAdd(&g_done, 1);
        if (t == L123_BLOCKS - 1) {
            __threadfence();
            double AP = 0.0, LR = 0.0, DS = 0.0;
            for (int i = 0; i < 4; i++) {
                int Hi = H0 >> i, Wi = W0 >> i;
                double Nd = (double)BB * 3.0 * (Hi - 2) * (Wi - 2);
                double Nl = (double)BB * 3.0 * Hi * Wi;
                double Np = (double)BB * Hi * Wi;
                const double* a = g_acc + i * 8;
                AP += 0.85 * (a[0] + a[1]) / Nd + 0.15 * (a[2] + a[3]) / Nl;
                LR += (a[4] + a[5]) / Np;
                DS += (a[6] + a[7]) / Np / (double)(1 << i);
            }
            AP *= 0.85;
            DS *= 0.1;
            double total = AP + LR + DS;
            out[0] = (float)total;
            out[1] = (float)AP;
            out[2] = (float)LR;
            out[3] = (float)DS;
            // self-clean for next graph replay (runs after all reads above)
            for (int i = 0; i < 32; i++) g_acc[i] = 0.0;
            g_done = 0;
            __threadfence();
        }
    }
}

// ---------------- host launcher ----------------
extern "C" void kernel_launch(void* const* d_in, const int* in_sizes, int n_in,
                              void* d_out, int out_size) {
    const float* disp0 = (const float*)d_in[0];
    const float* disp1 = (const float*)d_in[1];
    const float* disp2 = (const float*)d_in[2];
    const float* disp3 = (const float*)d_in[3];
    const float* left  = (const float*)d_in[4];
    const float* right = (const float*)d_in[5];
    float* out = (float*)d_out;

    static bool init = false;
    static float *lp1, *rp1, *lp2, *rp2, *lp3, *rp3;
    static cudaStream_t s1;
    static cudaEvent_t evStart, evResize;
    if (!init) {
        cudaGetSymbolAddress((void**)&lp1, g_lp1);
        cudaGetSymbolAddress((void**)&rp1, g_rp1);
        cudaGetSymbolAddress((void**)&lp2, g_lp2);
        cudaGetSymbolAddress((void**)&rp2, g_rp2);
        cudaGetSymbolAddress((void**)&lp3, g_lp3);
        cudaGetSymbolAddress((void**)&rp3, g_rp3);
        cudaStreamCreateWithFlags(&s1, cudaStreamNonBlocking);
        cudaEventCreateWithFlags(&evStart, cudaEventDisableTiming);
        cudaEventCreateWithFlags(&evResize, cudaEventDisableTiming);
        init = true;
    }

    LevelArgs args;
    args.lp[0] = left;  args.lp[1] = lp1; args.lp[2] = lp2; args.lp[3] = lp3;
    args.rp[0] = right; args.rp[1] = rp1; args.rp[2] = rp2; args.rp[3] = rp3;
    args.disp[0] = disp0; args.disp[1] = disp1; args.disp[2] = disp2; args.disp[3] = disp3;

    const int BC = BB * 3;

    // fork: side stream builds the pyramid while main stream runs fused L0
    cudaEventRecord(evStart, 0);
    cudaStreamWaitEvent(s1, evStart, 0);
    {
        int n1 = BC * 128 * 256;
        resize2_kernel<<<(2*n1 + 255) / 256, 256, 0, s1>>>(left, lp1, right, rp1, BC, 256, 512, 128, 256);
        int n2 = BC * 64 * 128;
        resize2_kernel<<<(2*n2 + 255) / 256, 256, 0, s1>>>(lp1, lp2, rp1, rp2, BC, 128, 256, 64, 128);
        int n3 = BC * 32 * 64;
        resize2_kernel<<<(2*n3 + 255) / 256, 256, 0, s1>>>(lp2, lp3, rp2, rp3, BC, 64, 128, 32, 64);
    }
    cudaEventRecord(evResize, s1);

    fused_kernel<<<L0_BLOCKS, NT>>>(args, 0, out);          // L0: no pyramid dependency

    cudaStreamWaitEvent(0, evResize, 0);                    // join
    fused_kernel<<<L123_BLOCKS, NT>>>(args, 1, out);        // L1-3 + tail combine
}